// round 9
// baseline (speedup 1.0000x reference)
#include <cuda_runtime.h>
#include <math.h>
#include <stdint.h>

// Problem constants
#define B_  16
#define S_  8192
#define H_  512
#define M_  (B_ * S_)

// GEMM tiling
#define BM 128
#define BN 256
#define BK 32
#define NSLICE 2            // 512 / BN
#define NCHUNK 16           // 512 / BK
#define NSTAGE 3
#define PAD 36              // smem row stride in floats

// ---------------- scratch ----------------
__device__ float g_qproj[B_ * H_];         // (B,H)
__device__ float g_part[NSLICE][M_];       // score partials per N-slice
__device__ float g_ctxpart[64][B_][H_];    // context partials

// ---------------- helpers ----------------
__device__ __forceinline__ uint32_t s2u(const void* p) {
    uint32_t a;
    asm("{ .reg .u64 t; cvta.to.shared.u64 t, %1; cvt.u32.u64 %0, t; }" : "=r"(a) : "l"(p));
    return a;
}
#define CP_ASYNC16(dst, src) \
    asm volatile("cp.async.cg.shared.global [%0], [%1], 16;" :: "r"(dst), "l"(src) : "memory")
#define CP_COMMIT()  asm volatile("cp.async.commit_group;" ::: "memory")
#define CP_WAIT1()   asm volatile("cp.async.wait_group 1;" ::: "memory")
#define CP_WAIT0()   asm volatile("cp.async.wait_group 0;" ::: "memory")

__device__ __forceinline__ void mma_tf32(float* d, const uint32_t* a, const uint32_t* b) {
    asm volatile(
        "mma.sync.aligned.m16n8k8.row.col.f32.tf32.tf32.f32 "
        "{%0,%1,%2,%3}, {%4,%5,%6,%7}, {%8,%9}, {%0,%1,%2,%3};"
        : "+f"(d[0]), "+f"(d[1]), "+f"(d[2]), "+f"(d[3])
        : "r"(a[0]), "r"(a[1]), "r"(a[2]), "r"(a[3]), "r"(b[0]), "r"(b[1]));
}

// ---------------- SMEM layout (dynamic) ----------------
// [0,1024)     sq (256 floats)
// [1024,2048)  sv (256 floats)
// [2048,4096)  red (128*4 floats)
// [4096,...)   A stages: 3 x 128*PAD*4 = 3 x 18432
// [...,...)    B stages: 3 x 256*PAD*4 = 3 x 36864
#define SM_A      4096
#define A_STAGE   (BM * PAD * 4)                 // 18432
#define SM_B      (SM_A + NSTAGE * A_STAGE)      // 59392
#define B_STAGE   (BN * PAD * 4)                 // 36864
#define SMEM_TOTAL (SM_B + NSTAGE * B_STAGE)     // 169984

// ---------------- kernel 1: q_proj ----------------
__global__ void qproj_kernel(const float* __restrict__ query,
                             const float* __restrict__ Wq)
{
    int w = threadIdx.x >> 5, lane = threadIdx.x & 31;
    int o = blockIdx.x * 8 + w;
    int b = blockIdx.y;
    const float* q  = query + b * H_;
    const float* wr = Wq + o * H_;
    float s = 0.f;
    #pragma unroll 4
    for (int k = lane; k < H_; k += 32) s += q[k] * wr[k];
    #pragma unroll
    for (int off = 16; off > 0; off >>= 1) s += __shfl_xor_sync(0xffffffffu, s, off);
    if (lane == 0) g_qproj[b * H_ + o] = s;
}

// ---------------- kernel 2: tf32 mma.sync GEMM + fused tanh/v epilogue ----------------
// 512 threads, 16 warps: 4 over M (32 rows) x 4 over N (64 cols). 3-stage pipeline.
__global__ __launch_bounds__(512, 1)
void score_gemm(const float* __restrict__ A,     // enc (M_, 512)
                const float* __restrict__ Wh,    // (512, 512)
                const float* __restrict__ v)
{
    extern __shared__ char smem[];
    const uint32_t smem_u = s2u(smem);
    float* sq  = (float*)smem;            // 256
    float* sv  = sq + 256;                // 256
    float* red = sv + 256;                // 128 x 4

    const int tid  = threadIdx.x;
    const int wid  = tid >> 5;
    const int lane = tid & 31;
    const int g    = lane >> 2;           // fragment row
    const int c    = lane & 3;            // fragment col group
    const int wm   = wid & 3;             // 4 warps over M: 32 rows each
    const int wn   = wid >> 2;            // 4 warps over N: 64 cols each

    const int bm    = blockIdx.x;
    const int slice = blockIdx.y;
    const int m0    = bm * BM;
    const int n0    = slice * BN;
    const int b     = m0 >> 13;

    for (int j = tid; j < 256; j += 512) {
        sq[j] = g_qproj[b * H_ + n0 + j];
        sv[j] = v[n0 + j];
    }

    // accumulators: 2 m-frags x 8 n-frags x 4 regs = 64
    float acc[2][8][4];
    #pragma unroll
    for (int i = 0; i < 2; i++)
        #pragma unroll
        for (int j = 0; j < 8; j++)
            #pragma unroll
            for (int k = 0; k < 4; k++) acc[i][j][k] = 0.f;

    const float* Abase = A + (size_t)m0 * H_;
    const float* Bbase = Wh + (size_t)n0 * H_;

    auto load_chunk = [&](int kc, int st) {
        const uint32_t abase = smem_u + SM_A + st * A_STAGE;
        const uint32_t bbase = smem_u + SM_B + st * B_STAGE;
        const float* As = Abase + kc * BK;
        const float* Bs = Bbase + kc * BK;
        #pragma unroll
        for (int i = 0; i < 2; i++) {             // A: 1024 16B units
            int id = tid + i * 512;
            int r = id >> 3, u = id & 7;
            CP_ASYNC16(abase + r * (PAD * 4) + u * 16, As + (size_t)r * H_ + u * 4);
        }
        #pragma unroll
        for (int i = 0; i < 4; i++) {             // B: 2048 16B units
            int id = tid + i * 512;
            int r = id >> 3, u = id & 7;
            CP_ASYNC16(bbase + r * (PAD * 4) + u * 16, Bs + (size_t)r * H_ + u * 4);
        }
        CP_COMMIT();
    };

    load_chunk(0, 0);
    load_chunk(1, 1);

    #pragma unroll 1
    for (int kc = 0; kc < NCHUNK; kc++) {
        const int st = kc % NSTAGE;
        if (kc + 2 < NCHUNK) CP_WAIT1(); else CP_WAIT0();
        __syncthreads();                          // data of chunk kc visible to all

        // prefetch chunk kc+2 into stage (kc+2)%NSTAGE (== stage of kc-1, already consumed)
        if (kc + 2 < NCHUNK) load_chunk(kc + 2, (kc + 2) % NSTAGE);

        const float* As = (const float*)(smem + SM_A + st * A_STAGE);
        const float* Bs = (const float*)(smem + SM_B + st * B_STAGE);

        #pragma unroll
        for (int ks = 0; ks < 4; ks++) {
            const int k0 = ks * 8;
            uint32_t afr[2][4];
            #pragma unroll
            for (int mf = 0; mf < 2; mf++) {
                const float* ap = As + (wm * 32 + mf * 16 + g) * PAD + k0 + c;
                afr[mf][0] = __float_as_uint(ap[0]);
                afr[mf][1] = __float_as_uint(ap[8 * PAD]);
                afr[mf][2] = __float_as_uint(ap[4]);
                afr[mf][3] = __float_as_uint(ap[8 * PAD + 4]);
            }
            uint32_t bfr[8][2];
            #pragma unroll
            for (int nf = 0; nf < 8; nf++) {
                const float* bp = Bs + (wn * 64 + nf * 8 + g) * PAD + k0 + c;
                bfr[nf][0] = __float_as_uint(bp[0]);
                bfr[nf][1] = __float_as_uint(bp[4]);
            }
            #pragma unroll
            for (int mf = 0; mf < 2; mf++)
                #pragma unroll
                for (int nf = 0; nf < 8; nf++)
                    mma_tf32(acc[mf][nf], afr[mf], bfr[nf]);
        }
    }

    // ---- epilogue: tanh(C + q) * v, reduce over this CTA's 256 columns ----
    float rowsum[4];
    #pragma unroll
    for (int i = 0; i < 4; i++) rowsum[i] = 0.f;

    #pragma unroll
    for (int mf = 0; mf < 2; mf++) {
        #pragma unroll
        for (int nf = 0; nf < 8; nf++) {
            const int cb = wn * 64 + nf * 8 + 2 * c;   // slice-local column
            const float q0 = sq[cb],     v0 = sv[cb];
            const float q1 = sq[cb + 1], v1 = sv[cb + 1];
            rowsum[mf * 2 + 0] += tanhf(acc[mf][nf][0] + q0) * v0
                                + tanhf(acc[mf][nf][1] + q1) * v1;
            rowsum[mf * 2 + 1] += tanhf(acc[mf][nf][2] + q0) * v0
                                + tanhf(acc[mf][nf][3] + q1) * v1;
        }
    }
    #pragma unroll
    for (int i = 0; i < 4; i++) {
        rowsum[i] += __shfl_xor_sync(0xffffffffu, rowsum[i], 1);
        rowsum[i] += __shfl_xor_sync(0xffffffffu, rowsum[i], 2);
    }
    __syncthreads();                          // done reading sq/sv? (red aliasing safety)
    if (c == 0) {
        #pragma unroll
        for (int i = 0; i < 4; i++) {
            const int mf = i >> 1, h = i & 1;
            const int row = wm * 32 + mf * 16 + g + h * 8;   // 0..127
            red[row * 4 + wn] = rowsum[i];
        }
    }
    __syncthreads();
    if (tid < BM) {
        g_part[slice][m0 + tid] = red[tid * 4 + 0] + red[tid * 4 + 1]
                                + red[tid * 4 + 2] + red[tid * 4 + 3];
    }
}

// ---------------- kernel 3: softmax ----------------
__global__ __launch_bounds__(1024)
void softmax_kernel(float* __restrict__ out_alpha)
{
    __shared__ float sm[32];
    const int b = blockIdx.x, tid = threadIdx.x;
    const int w = tid >> 5, lane = tid & 31;

    float sc[8];
    float mx = -1e30f;
    #pragma unroll
    for (int i = 0; i < 8; i++) {
        int m = b * S_ + tid + i * 1024;
        float x = g_part[0][m] + g_part[1][m];
        sc[i] = x;
        mx = fmaxf(mx, x);
    }
    #pragma unroll
    for (int off = 16; off > 0; off >>= 1) mx = fmaxf(mx, __shfl_xor_sync(0xffffffffu, mx, off));
    if (lane == 0) sm[w] = mx;
    __syncthreads();
    if (tid < 32) {
        float t = sm[tid];
        #pragma unroll
        for (int off = 16; off > 0; off >>= 1) t = fmaxf(t, __shfl_xor_sync(0xffffffffu, t, off));
        if (tid == 0) sm[0] = t;
    }
    __syncthreads();
    mx = sm[0];
    __syncthreads();

    float tot = 0.f;
    #pragma unroll
    for (int i = 0; i < 8; i++) { sc[i] = expf(sc[i] - mx); tot += sc[i]; }
    #pragma unroll
    for (int off = 16; off > 0; off >>= 1) tot += __shfl_xor_sync(0xffffffffu, tot, off);
    if (lane == 0) sm[w] = tot;
    __syncthreads();
    if (tid < 32) {
        float t = sm[tid];
        #pragma unroll
        for (int off = 16; off > 0; off >>= 1) t += __shfl_xor_sync(0xffffffffu, t, off);
        if (tid == 0) sm[0] = t;
    }
    __syncthreads();
    float inv = 1.f / sm[0];

    #pragma unroll
    for (int i = 0; i < 8; i++)
        out_alpha[b * S_ + tid + i * 1024] = sc[i] * inv;
}

// ---------------- kernel 4: context partials (float4 per thread) ----------------
__global__ __launch_bounds__(128)
void ctx_part_kernel(const float* __restrict__ enc,
                     const float* __restrict__ alpha)
{
    __shared__ float al[128];
    const int sch = blockIdx.x, b = blockIdx.y;
    const int tid = threadIdx.x;
    const int s0  = sch * 128;
    al[tid] = alpha[b * S_ + s0 + tid];
    __syncthreads();
    const float4* e = (const float4*)(enc + ((size_t)b * S_ + s0) * H_) + tid;
    float4 acc = make_float4(0.f, 0.f, 0.f, 0.f);
    #pragma unroll 8
    for (int s = 0; s < 128; s++) {
        float4 t = e[(size_t)s * (H_ / 4)];
        float  w = al[s];
        acc.x += w * t.x; acc.y += w * t.y;
        acc.z += w * t.z; acc.w += w * t.w;
    }
    ((float4*)&g_ctxpart[sch][b][0])[tid] = acc;
}

// ---------------- kernel 5: reduce context partials ----------------
__global__ __launch_bounds__(512)
void ctx_reduce_kernel(float* __restrict__ out_ctx)
{
    const int b = blockIdx.x, h = threadIdx.x;
    float s = 0.f;
    #pragma unroll
    for (int cidx = 0; cidx < 64; cidx++) s += g_ctxpart[cidx][b][h];
    out_ctx[b * H_ + h] = s;
}

// ---------------- launcher ----------------
extern "C" void kernel_launch(void* const* d_in, const int* in_sizes, int n_in,
                              void* d_out, int out_size)
{
    const float* enc   = (const float*)d_in[0];
    const float* query = (const float*)d_in[1];
    const float* Wh    = (const float*)d_in[2];
    const float* Wq    = (const float*)d_in[3];
    const float* v     = (const float*)d_in[4];

    float* out       = (float*)d_out;
    float* out_ctx   = out;
    float* out_alpha = out + B_ * H_;

    cudaFuncSetAttribute(score_gemm, cudaFuncAttributeMaxDynamicSharedMemorySize, SMEM_TOTAL);

    qproj_kernel   <<<dim3(H_ / 8, B_), 256>>>(query, Wq);
    score_gemm     <<<dim3(M_ / BM, NSLICE), 512, SMEM_TOTAL>>>(enc, Wh, v);
    softmax_kernel <<<B_, 1024>>>(out_alpha);
    ctx_part_kernel<<<dim3(64, B_), 128>>>(enc, out_alpha);
    ctx_reduce_kernel<<<B_, 512>>>(out_ctx);
}

// round 13
// speedup vs baseline: 1.3412x; 1.3412x over previous
#include <cuda_runtime.h>
#include <math.h>
#include <stdint.h>

// Problem constants
#define B_  16
#define S_  8192
#define H_  512
#define M_  (B_ * S_)

// GEMM tiling
#define BM 128
#define BN 128
#define BK 32
#define NSLICE 4            // 512 / BN
#define NCHUNK 16           // 512 / BK
#define NSTAGE 3

// ---------------- scratch ----------------
__device__ float g_qproj[B_ * H_];         // (B,H)
__device__ float g_part[NSLICE][M_];       // score partials per N-slice
__device__ float g_ctxpart[64][B_][H_];    // context partials

// ---------------- helpers ----------------
__device__ __forceinline__ uint32_t s2u(const void* p) {
    uint32_t a;
    asm("{ .reg .u64 t; cvta.to.shared.u64 t, %1; cvt.u32.u64 %0, t; }" : "=r"(a) : "l"(p));
    return a;
}
#define CP_ASYNC16(dst, src) \
    asm volatile("cp.async.cg.shared.global [%0], [%1], 16;" :: "r"(dst), "l"(src) : "memory")
#define CP_COMMIT()  asm volatile("cp.async.commit_group;" ::: "memory")
#define CP_WAIT1()   asm volatile("cp.async.wait_group 1;" ::: "memory")
#define CP_WAIT0()   asm volatile("cp.async.wait_group 0;" ::: "memory")

__device__ __forceinline__ void mma_tf32(float* d, const uint32_t* a, const uint32_t* b) {
    asm volatile(
        "mma.sync.aligned.m16n8k8.row.col.f32.tf32.tf32.f32 "
        "{%0,%1,%2,%3}, {%4,%5,%6,%7}, {%8,%9}, {%0,%1,%2,%3};"
        : "+f"(d[0]), "+f"(d[1]), "+f"(d[2]), "+f"(d[3])
        : "r"(a[0]), "r"(a[1]), "r"(a[2]), "r"(a[3]), "r"(b[0]), "r"(b[1]));
}

// XOR-swizzled byte offset for row r (128B/row), float column j.
// 16B unit u = j>>2 swizzled by r&7; conflict-free for both cp.async stores
// (8 rows x 8 units per warp hit distinct banks) and fragment LDS
// (banks ((u^g)*4+c) cover all 32).
__device__ __forceinline__ uint32_t swz(int r, int j) {
    return (uint32_t)(r * 128 + ((((j >> 2) ^ (r & 7)) ) << 4) + (j & 3) * 4);
}

// ---------------- SMEM layout (dynamic) ----------------
// [0,512)     sq (128 floats)
// [512,1024)  sv (128 floats)
// [1024,3072) red (128*4 floats)
// [3072,...)  A stages: 3 x 16384
// [...,...)   B stages: 3 x 16384
#define SM_A      3072
#define A_STAGE   16384
#define SM_B      (SM_A + NSTAGE * A_STAGE)      // 52224
#define B_STAGE   16384
#define SMEM_TOTAL (SM_B + NSTAGE * B_STAGE)     // 101376 -> 2 CTAs/SM

// ---------------- kernel 1: q_proj ----------------
__global__ void qproj_kernel(const float* __restrict__ query,
                             const float* __restrict__ Wq)
{
    int w = threadIdx.x >> 5, lane = threadIdx.x & 31;
    int o = blockIdx.x * 8 + w;
    int b = blockIdx.y;
    const float* q  = query + b * H_;
    const float* wr = Wq + o * H_;
    float s = 0.f;
    #pragma unroll 4
    for (int k = lane; k < H_; k += 32) s += q[k] * wr[k];
    #pragma unroll
    for (int off = 16; off > 0; off >>= 1) s += __shfl_xor_sync(0xffffffffu, s, off);
    if (lane == 0) g_qproj[b * H_ + o] = s;
}

// ---------------- kernel 2: tf32 mma.sync GEMM + fused tanh/v epilogue ----------------
// 256 threads, 8 warps: 2 over M (64 rows) x 4 over N (32 cols).
// 3-stage cp.async pipeline, ONE __syncthreads per chunk, 2 CTAs/SM.
__global__ __launch_bounds__(256, 2)
void score_gemm(const float* __restrict__ A,     // enc (M_, 512)
                const float* __restrict__ Wh,    // (512, 512)
                const float* __restrict__ v)
{
    extern __shared__ char smem[];
    const uint32_t smem_u = s2u(smem);
    float* sq  = (float*)smem;            // 128
    float* sv  = sq + 128;                // 128
    float* red = sv + 128;                // 128 x 4

    const int tid  = threadIdx.x;
    const int wid  = tid >> 5;
    const int lane = tid & 31;
    const int g    = lane >> 2;           // fragment row
    const int c    = lane & 3;            // fragment col group
    const int wm   = wid & 1;             // 2 warps over M: 64 rows each
    const int wn   = wid >> 1;            // 4 warps over N: 32 cols each

    const int slice = blockIdx.x;         // slice-fast: 4 slices of one bm adjacent
    const int bm    = blockIdx.y;
    const int m0    = bm * BM;
    const int n0    = slice * BN;
    const int b     = m0 >> 13;

    if (tid < 128) {
        sq[tid] = g_qproj[b * H_ + n0 + tid];
        sv[tid] = v[n0 + tid];
    }

    // accumulators: 4 m-frags x 4 n-frags x 4 regs
    float acc[4][4][4];
    #pragma unroll
    for (int i = 0; i < 4; i++)
        #pragma unroll
        for (int j = 0; j < 4; j++)
            #pragma unroll
            for (int k = 0; k < 4; k++) acc[i][j][k] = 0.f;

    const float* Abase = A + (size_t)m0 * H_;
    const float* Bbase = Wh + (size_t)n0 * H_;

    auto load_chunk = [&](int kc, int st) {
        const uint32_t abase = smem_u + SM_A + st * A_STAGE;
        const uint32_t bbase = smem_u + SM_B + st * B_STAGE;
        const float* As = Abase + kc * BK;
        const float* Bs = Bbase + kc * BK;
        #pragma unroll
        for (int i = 0; i < 4; i++) {             // A: 1024 16B units
            int id = tid + i * 256;
            int r = id >> 3, u = id & 7;
            CP_ASYNC16(abase + r * 128 + ((u ^ (r & 7)) << 4), As + (size_t)r * H_ + u * 4);
        }
        #pragma unroll
        for (int i = 0; i < 4; i++) {             // B: 1024 16B units
            int id = tid + i * 256;
            int r = id >> 3, u = id & 7;
            CP_ASYNC16(bbase + r * 128 + ((u ^ (r & 7)) << 4), Bs + (size_t)r * H_ + u * 4);
        }
        CP_COMMIT();
    };

    load_chunk(0, 0);
    load_chunk(1, 1);

    #pragma unroll 1
    for (int kc = 0; kc < NCHUNK; kc++) {
        const int st = kc % NSTAGE;
        if (kc + 2 < NCHUNK) CP_WAIT1(); else CP_WAIT0();
        __syncthreads();                          // chunk kc visible; stage (kc-1) consumed

        if (kc + 2 < NCHUNK) load_chunk(kc + 2, (kc + 2) % NSTAGE);

        const char* As = smem + SM_A + st * A_STAGE;
        const char* Bs = smem + SM_B + st * B_STAGE;

        #pragma unroll
        for (int ks = 0; ks < 4; ks++) {
            const int k0 = ks * 8;
            uint32_t afr[4][4];
            #pragma unroll
            for (int mf = 0; mf < 4; mf++) {
                const int r = wm * 64 + mf * 16 + g;
                afr[mf][0] = *(const uint32_t*)(As + swz(r,     k0 + c));
                afr[mf][1] = *(const uint32_t*)(As + swz(r + 8, k0 + c));
                afr[mf][2] = *(const uint32_t*)(As + swz(r,     k0 + c + 4));
                afr[mf][3] = *(const uint32_t*)(As + swz(r + 8, k0 + c + 4));
            }
            uint32_t bfr[4][2];
            #pragma unroll
            for (int nf = 0; nf < 4; nf++) {
                const int r = wn * 32 + nf * 8 + g;
                bfr[nf][0] = *(const uint32_t*)(Bs + swz(r, k0 + c));
                bfr[nf][1] = *(const uint32_t*)(Bs + swz(r, k0 + c + 4));
            }
            #pragma unroll
            for (int mf = 0; mf < 4; mf++)
                #pragma unroll
                for (int nf = 0; nf < 4; nf++)
                    mma_tf32(acc[mf][nf], afr[mf], bfr[nf]);
        }
    }

    // ---- epilogue: tanh(C + q) * v, reduce over this CTA's 128 columns ----
    float rowsum[8];
    #pragma unroll
    for (int i = 0; i < 8; i++) rowsum[i] = 0.f;

    #pragma unroll
    for (int mf = 0; mf < 4; mf++) {
        #pragma unroll
        for (int nf = 0; nf < 4; nf++) {
            const int cb = wn * 32 + nf * 8 + 2 * c;
            const float q0 = sq[cb],     v0 = sv[cb];
            const float q1 = sq[cb + 1], v1 = sv[cb + 1];
            rowsum[mf * 2 + 0] += tanhf(acc[mf][nf][0] + q0) * v0
                                + tanhf(acc[mf][nf][1] + q1) * v1;
            rowsum[mf * 2 + 1] += tanhf(acc[mf][nf][2] + q0) * v0
                                + tanhf(acc[mf][nf][3] + q1) * v1;
        }
    }
    #pragma unroll
    for (int i = 0; i < 8; i++) {
        rowsum[i] += __shfl_xor_sync(0xffffffffu, rowsum[i], 1);
        rowsum[i] += __shfl_xor_sync(0xffffffffu, rowsum[i], 2);
    }
    if (c == 0) {
        #pragma unroll
        for (int i = 0; i < 8; i++) {
            const int mf = i >> 1, h = i & 1;
            const int row = wm * 64 + mf * 16 + g + h * 8;   // 0..127
            red[row * 4 + wn] = rowsum[i];
        }
    }
    __syncthreads();
    if (tid < BM) {
        g_part[slice][m0 + tid] = red[tid * 4 + 0] + red[tid * 4 + 1]
                                + red[tid * 4 + 2] + red[tid * 4 + 3];
    }
}

// ---------------- kernel 3: softmax ----------------
__global__ __launch_bounds__(1024)
void softmax_kernel(float* __restrict__ out_alpha)
{
    __shared__ float sm[32];
    const int b = blockIdx.x, tid = threadIdx.x;
    const int w = tid >> 5, lane = tid & 31;

    float sc[8];
    float mx = -1e30f;
    #pragma unroll
    for (int i = 0; i < 8; i++) {
        int m = b * S_ + tid + i * 1024;
        float x = g_part[0][m] + g_part[1][m] + g_part[2][m] + g_part[3][m];
        sc[i] = x;
        mx = fmaxf(mx, x);
    }
    #pragma unroll
    for (int off = 16; off > 0; off >>= 1) mx = fmaxf(mx, __shfl_xor_sync(0xffffffffu, mx, off));
    if (lane == 0) sm[w] = mx;
    __syncthreads();
    if (tid < 32) {
        float t = sm[tid];
        #pragma unroll
        for (int off = 16; off > 0; off >>= 1) t = fmaxf(t, __shfl_xor_sync(0xffffffffu, t, off));
        if (tid == 0) sm[0] = t;
    }
    __syncthreads();
    mx = sm[0];
    __syncthreads();

    float tot = 0.f;
    #pragma unroll
    for (int i = 0; i < 8; i++) { sc[i] = expf(sc[i] - mx); tot += sc[i]; }
    #pragma unroll
    for (int off = 16; off > 0; off >>= 1) tot += __shfl_xor_sync(0xffffffffu, tot, off);
    if (lane == 0) sm[w] = tot;
    __syncthreads();
    if (tid < 32) {
        float t = sm[tid];
        #pragma unroll
        for (int off = 16; off > 0; off >>= 1) t += __shfl_xor_sync(0xffffffffu, t, off);
        if (tid == 0) sm[0] = t;
    }
    __syncthreads();
    float inv = 1.f / sm[0];

    #pragma unroll
    for (int i = 0; i < 8; i++)
        out_alpha[b * S_ + tid + i * 1024] = sc[i] * inv;
}

// ---------------- kernel 4: context partials (float4 per thread) ----------------
__global__ __launch_bounds__(128)
void ctx_part_kernel(const float* __restrict__ enc,
                     const float* __restrict__ alpha)
{
    __shared__ float al[128];
    const int sch = blockIdx.x, b = blockIdx.y;
    const int tid = threadIdx.x;
    const int s0  = sch * 128;
    al[tid] = alpha[b * S_ + s0 + tid];
    __syncthreads();
    const float4* e = (const float4*)(enc + ((size_t)b * S_ + s0) * H_) + tid;
    float4 acc = make_float4(0.f, 0.f, 0.f, 0.f);
    #pragma unroll 8
    for (int s = 0; s < 128; s++) {
        float4 t = e[(size_t)s * (H_ / 4)];
        float  w = al[s];
        acc.x += w * t.x; acc.y += w * t.y;
        acc.z += w * t.z; acc.w += w * t.w;
    }
    ((float4*)&g_ctxpart[sch][b][0])[tid] = acc;
}

// ---------------- kernel 5: reduce context partials ----------------
__global__ __launch_bounds__(512)
void ctx_reduce_kernel(float* __restrict__ out_ctx)
{
    const int b = blockIdx.x, h = threadIdx.x;
    float s = 0.f;
    #pragma unroll
    for (int cidx = 0; cidx < 64; cidx++) s += g_ctxpart[cidx][b][h];
    out_ctx[b * H_ + h] = s;
}

// ---------------- launcher ----------------
extern "C" void kernel_launch(void* const* d_in, const int* in_sizes, int n_in,
                              void* d_out, int out_size)
{
    const float* enc   = (const float*)d_in[0];
    const float* query = (const float*)d_in[1];
    const float* Wh    = (const float*)d_in[2];
    const float* Wq    = (const float*)d_in[3];
    const float* v     = (const float*)d_in[4];

    float* out       = (float*)d_out;
    float* out_ctx   = out;
    float* out_alpha = out + B_ * H_;

    cudaFuncSetAttribute(score_gemm, cudaFuncAttributeMaxDynamicSharedMemorySize, SMEM_TOTAL);

    qproj_kernel   <<<dim3(H_ / 8, B_), 256>>>(query, Wq);
    score_gemm     <<<dim3(NSLICE, M_ / BM), 256, SMEM_TOTAL>>>(enc, Wh, v);
    softmax_kernel <<<B_, 1024>>>(out_alpha);
    ctx_part_kernel<<<dim3(64, B_), 128>>>(enc, out_alpha);
    ctx_reduce_kernel<<<B_, 512>>>(out_ctx);
}

// round 14
// speedup vs baseline: 1.4199x; 1.0587x over previous
#include <cuda_runtime.h>
#include <math.h>
#include <stdint.h>

// Problem constants
#define B_  16
#define S_  8192
#define H_  512
#define M_  (B_ * S_)

// GEMM tiling
#define BM 128
#define BN 128
#define BK 32
#define NSLICE 4            // 512 / BN
#define NCHUNK 16           // 512 / BK
#define NSTAGE 3

// ---------------- scratch ----------------
__device__ float g_qproj[B_ * H_];         // (B,H)
__device__ float g_part[NSLICE][M_];       // score partials per N-slice
__device__ float g_ctxpart[64][B_][H_];    // context partials

// ---------------- helpers ----------------
__device__ __forceinline__ uint32_t s2u(const void* p) {
    uint32_t a;
    asm("{ .reg .u64 t; cvta.to.shared.u64 t, %1; cvt.u32.u64 %0, t; }" : "=r"(a) : "l"(p));
    return a;
}
#define CP_ASYNC16(dst, src) \
    asm volatile("cp.async.cg.shared.global [%0], [%1], 16;" :: "r"(dst), "l"(src) : "memory")
#define CP_COMMIT()  asm volatile("cp.async.commit_group;" ::: "memory")
#define CP_WAIT1()   asm volatile("cp.async.wait_group 1;" ::: "memory")
#define CP_WAIT0()   asm volatile("cp.async.wait_group 0;" ::: "memory")

__device__ __forceinline__ void mma_tf32(float* d, const uint32_t* a, const uint32_t* b) {
    asm volatile(
        "mma.sync.aligned.m16n8k8.row.col.f32.tf32.tf32.f32 "
        "{%0,%1,%2,%3}, {%4,%5,%6,%7}, {%8,%9}, {%0,%1,%2,%3};"
        : "+f"(d[0]), "+f"(d[1]), "+f"(d[2]), "+f"(d[3])
        : "r"(a[0]), "r"(a[1]), "r"(a[2]), "r"(a[3]), "r"(b[0]), "r"(b[1]));
}

// ldmatrix: each 8x8 b16 matrix row = 16B = 4 f32. Treating f32 as b16-pairs,
// x4 delivers a full tf32 A fragment in mma register order; x2 a B fragment.
__device__ __forceinline__ void ldsm_x4(uint32_t* r, uint32_t addr) {
    asm volatile("ldmatrix.sync.aligned.m8n8.x4.shared.b16 {%0,%1,%2,%3}, [%4];"
        : "=r"(r[0]), "=r"(r[1]), "=r"(r[2]), "=r"(r[3]) : "r"(addr));
}
__device__ __forceinline__ void ldsm_x2(uint32_t* r, uint32_t addr) {
    asm volatile("ldmatrix.sync.aligned.m8n8.x2.shared.b16 {%0,%1}, [%2];"
        : "=r"(r[0]), "=r"(r[1]) : "r"(addr));
}

// ---------------- SMEM layout (dynamic) ----------------
// [0,512)     sq (128 floats)
// [512,1024)  sv (128 floats)
// [1024,3072) red (128*4 floats)
// [3072,...)  A stages: 3 x 16384
// [...,...)   B stages: 3 x 16384
#define SM_A      3072
#define A_STAGE   16384
#define SM_B      (SM_A + NSTAGE * A_STAGE)      // 52224
#define B_STAGE   16384
#define SMEM_TOTAL (SM_B + NSTAGE * B_STAGE)     // 101376 -> 2 CTAs/SM

// ---------------- kernel 1: q_proj ----------------
__global__ void qproj_kernel(const float* __restrict__ query,
                             const float* __restrict__ Wq)
{
    int w = threadIdx.x >> 5, lane = threadIdx.x & 31;
    int o = blockIdx.x * 8 + w;
    int b = blockIdx.y;
    const float* q  = query + b * H_;
    const float* wr = Wq + o * H_;
    float s = 0.f;
    #pragma unroll 4
    for (int k = lane; k < H_; k += 32) s += q[k] * wr[k];
    #pragma unroll
    for (int off = 16; off > 0; off >>= 1) s += __shfl_xor_sync(0xffffffffu, s, off);
    if (lane == 0) g_qproj[b * H_ + o] = s;
}

// ---------------- kernel 2: tf32 mma.sync GEMM + fused tanh/v epilogue ----------------
// 256 threads, 8 warps: 2 over M (64 rows) x 4 over N (32 cols).
// 3-stage cp.async pipeline, one __syncthreads per chunk, 2 CTAs/SM,
// ldmatrix fragment loads (24 LDSM/chunk/warp instead of 96 LDS.32/thread).
__global__ __launch_bounds__(256, 2)
void score_gemm(const float* __restrict__ A,     // enc (M_, 512)
                const float* __restrict__ Wh,    // (512, 512)
                const float* __restrict__ v)
{
    extern __shared__ char smem[];
    const uint32_t smem_u = s2u(smem);
    float* sq  = (float*)smem;            // 128
    float* sv  = sq + 128;                // 128
    float* red = sv + 128;                // 128 x 4

    const int tid  = threadIdx.x;
    const int wid  = tid >> 5;
    const int lane = tid & 31;
    const int g    = lane >> 2;           // fragment row
    const int c    = lane & 3;            // fragment col group
    const int wm   = wid & 1;             // 2 warps over M: 64 rows each
    const int wn   = wid >> 1;            // 4 warps over N: 32 cols each

    // ldmatrix source-lane roles
    const int q8  = lane >> 3;            // which 8x8 matrix this lane addresses
    const int rw  = lane & 7;             // row within matrix; also swizzle selector
    const int duA = q8 >> 1;              // A: matrices 2,3 are the +4-column half
    const int roA = (q8 & 1) << 3;        // A: matrices 1,3 are the +8-row half
    const int duB = q8 & 1;               // B x2: matrix 1 is the +4-column half

    const int slice = blockIdx.x;         // slice-fast: 4 slices of one bm adjacent
    const int bm    = blockIdx.y;
    const int m0    = bm * BM;
    const int n0    = slice * BN;
    const int b     = m0 >> 13;

    if (tid < 128) {
        sq[tid] = g_qproj[b * H_ + n0 + tid];
        sv[tid] = v[n0 + tid];
    }

    // per-thread ldmatrix row bases (byte offsets within a stage)
    uint32_t aRow[4], bRow[4];
    #pragma unroll
    for (int mf = 0; mf < 4; mf++) aRow[mf] = (uint32_t)(wm * 64 + mf * 16 + roA + rw) * 128;
    #pragma unroll
    for (int nf = 0; nf < 4; nf++) bRow[nf] = (uint32_t)(wn * 32 + nf * 8 + rw) * 128;

    // accumulators: 4 m-frags x 4 n-frags x 4 regs
    float acc[4][4][4];
    #pragma unroll
    for (int i = 0; i < 4; i++)
        #pragma unroll
        for (int j = 0; j < 4; j++)
            #pragma unroll
            for (int k = 0; k < 4; k++) acc[i][j][k] = 0.f;

    const float* Abase = A + (size_t)m0 * H_;
    const float* Bbase = Wh + (size_t)n0 * H_;

    auto load_chunk = [&](int kc, int st) {
        const uint32_t abase = smem_u + SM_A + st * A_STAGE;
        const uint32_t bbase = smem_u + SM_B + st * B_STAGE;
        const float* As = Abase + kc * BK;
        const float* Bs = Bbase + kc * BK;
        #pragma unroll
        for (int i = 0; i < 4; i++) {             // A: 1024 16B units
            int id = tid + i * 256;
            int r = id >> 3, u = id & 7;
            CP_ASYNC16(abase + r * 128 + ((u ^ (r & 7)) << 4), As + (size_t)r * H_ + u * 4);
        }
        #pragma unroll
        for (int i = 0; i < 4; i++) {             // B: 1024 16B units
            int id = tid + i * 256;
            int r = id >> 3, u = id & 7;
            CP_ASYNC16(bbase + r * 128 + ((u ^ (r & 7)) << 4), Bs + (size_t)r * H_ + u * 4);
        }
        CP_COMMIT();
    };

    load_chunk(0, 0);
    load_chunk(1, 1);

    #pragma unroll 1
    for (int kc = 0; kc < NCHUNK; kc++) {
        const int st = kc % NSTAGE;
        if (kc + 2 < NCHUNK) CP_WAIT1(); else CP_WAIT0();
        __syncthreads();                          // chunk kc visible; stage (kc-1) consumed

        if (kc + 2 < NCHUNK) load_chunk(kc + 2, (kc + 2) % NSTAGE);

        const uint32_t abase = smem_u + SM_A + st * A_STAGE;
        const uint32_t bbase = smem_u + SM_B + st * B_STAGE;

        #pragma unroll
        for (int ks = 0; ks < 4; ks++) {
            const int k2 = ks * 2;                // 16B unit of this k-step
            const uint32_t axor = (uint32_t)(((k2 + duA) ^ rw) << 4);
            const uint32_t bxor = (uint32_t)(((k2 + duB) ^ rw) << 4);

            uint32_t afr[4][4];
            #pragma unroll
            for (int mf = 0; mf < 4; mf++)
                ldsm_x4(afr[mf], abase + aRow[mf] + axor);

            uint32_t bfr[4][2];
            #pragma unroll
            for (int nf = 0; nf < 4; nf++)
                ldsm_x2(bfr[nf], bbase + bRow[nf] + bxor);

            #pragma unroll
            for (int mf = 0; mf < 4; mf++)
                #pragma unroll
                for (int nf = 0; nf < 4; nf++)
                    mma_tf32(acc[mf][nf], afr[mf], bfr[nf]);
        }
    }

    // ---- epilogue: tanh(C + q) * v, reduce over this CTA's 128 columns ----
    float rowsum[8];
    #pragma unroll
    for (int i = 0; i < 8; i++) rowsum[i] = 0.f;

    #pragma unroll
    for (int mf = 0; mf < 4; mf++) {
        #pragma unroll
        for (int nf = 0; nf < 4; nf++) {
            const int cb = wn * 32 + nf * 8 + 2 * c;
            const float q0 = sq[cb],     v0 = sv[cb];
            const float q1 = sq[cb + 1], v1 = sv[cb + 1];
            rowsum[mf * 2 + 0] += tanhf(acc[mf][nf][0] + q0) * v0
                                + tanhf(acc[mf][nf][1] + q1) * v1;
            rowsum[mf * 2 + 1] += tanhf(acc[mf][nf][2] + q0) * v0
                                + tanhf(acc[mf][nf][3] + q1) * v1;
        }
    }
    #pragma unroll
    for (int i = 0; i < 8; i++) {
        rowsum[i] += __shfl_xor_sync(0xffffffffu, rowsum[i], 1);
        rowsum[i] += __shfl_xor_sync(0xffffffffu, rowsum[i], 2);
    }
    if (c == 0) {
        #pragma unroll
        for (int i = 0; i < 8; i++) {
            const int mf = i >> 1, h = i & 1;
            const int row = wm * 64 + mf * 16 + g + h * 8;   // 0..127
            red[row * 4 + wn] = rowsum[i];
        }
    }
    __syncthreads();
    if (tid < BM) {
        g_part[slice][m0 + tid] = red[tid * 4 + 0] + red[tid * 4 + 1]
                                + red[tid * 4 + 2] + red[tid * 4 + 3];
    }
}

// ---------------- kernel 3: softmax ----------------
__global__ __launch_bounds__(1024)
void softmax_kernel(float* __restrict__ out_alpha)
{
    __shared__ float sm[32];
    const int b = blockIdx.x, tid = threadIdx.x;
    const int w = tid >> 5, lane = tid & 31;

    float sc[8];
    float mx = -1e30f;
    #pragma unroll
    for (int i = 0; i < 8; i++) {
        int m = b * S_ + tid + i * 1024;
        float x = g_part[0][m] + g_part[1][m] + g_part[2][m] + g_part[3][m];
        sc[i] = x;
        mx = fmaxf(mx, x);
    }
    #pragma unroll
    for (int off = 16; off > 0; off >>= 1) mx = fmaxf(mx, __shfl_xor_sync(0xffffffffu, mx, off));
    if (lane == 0) sm[w] = mx;
    __syncthreads();
    if (tid < 32) {
        float t = sm[tid];
        #pragma unroll
        for (int off = 16; off > 0; off >>= 1) t = fmaxf(t, __shfl_xor_sync(0xffffffffu, t, off));
        if (tid == 0) sm[0] = t;
    }
    __syncthreads();
    mx = sm[0];
    __syncthreads();

    float tot = 0.f;
    #pragma unroll
    for (int i = 0; i < 8; i++) { sc[i] = expf(sc[i] - mx); tot += sc[i]; }
    #pragma unroll
    for (int off = 16; off > 0; off >>= 1) tot += __shfl_xor_sync(0xffffffffu, tot, off);
    if (lane == 0) sm[w] = tot;
    __syncthreads();
    if (tid < 32) {
        float t = sm[tid];
        #pragma unroll
        for (int off = 16; off > 0; off >>= 1) t += __shfl_xor_sync(0xffffffffu, t, off);
        if (tid == 0) sm[0] = t;
    }
    __syncthreads();
    float inv = 1.f / sm[0];

    #pragma unroll
    for (int i = 0; i < 8; i++)
        out_alpha[b * S_ + tid + i * 1024] = sc[i] * inv;
}

// ---------------- kernel 4: context partials (float4 per thread) ----------------
__global__ __launch_bounds__(128)
void ctx_part_kernel(const float* __restrict__ enc,
                     const float* __restrict__ alpha)
{
    __shared__ float al[128];
    const int sch = blockIdx.x, b = blockIdx.y;
    const int tid = threadIdx.x;
    const int s0  = sch * 128;
    al[tid] = alpha[b * S_ + s0 + tid];
    __syncthreads();
    const float4* e = (const float4*)(enc + ((size_t)b * S_ + s0) * H_) + tid;
    float4 acc = make_float4(0.f, 0.f, 0.f, 0.f);
    #pragma unroll 8
    for (int s = 0; s < 128; s++) {
        float4 t = e[(size_t)s * (H_ / 4)];
        float  w = al[s];
        acc.x += w * t.x; acc.y += w * t.y;
        acc.z += w * t.z; acc.w += w * t.w;
    }
    ((float4*)&g_ctxpart[sch][b][0])[tid] = acc;
}

// ---------------- kernel 5: reduce context partials ----------------
__global__ __launch_bounds__(512)
void ctx_reduce_kernel(float* __restrict__ out_ctx)
{
    const int b = blockIdx.x, h = threadIdx.x;
    float s = 0.f;
    #pragma unroll
    for (int cidx = 0; cidx < 64; cidx++) s += g_ctxpart[cidx][b][h];
    out_ctx[b * H_ + h] = s;
}

// ---------------- launcher ----------------
extern "C" void kernel_launch(void* const* d_in, const int* in_sizes, int n_in,
                              void* d_out, int out_size)
{
    const float* enc   = (const float*)d_in[0];
    const float* query = (const float*)d_in[1];
    const float* Wh    = (const float*)d_in[2];
    const float* Wq    = (const float*)d_in[3];
    const float* v     = (const float*)d_in[4];

    float* out       = (float*)d_out;
    float* out_ctx   = out;
    float* out_alpha = out + B_ * H_;

    cudaFuncSetAttribute(score_gemm, cudaFuncAttributeMaxDynamicSharedMemorySize, SMEM_TOTAL);

    qproj_kernel   <<<dim3(H_ / 8, B_), 256>>>(query, Wq);
    score_gemm     <<<dim3(NSLICE, M_ / BM), 256, SMEM_TOTAL>>>(enc, Wh, v);
    softmax_kernel <<<B_, 1024>>>(out_alpha);
    ctx_part_kernel<<<dim3(64, B_), 128>>>(enc, out_alpha);
    ctx_reduce_kernel<<<B_, 512>>>(out_ctx);
}

// round 15
// speedup vs baseline: 1.8191x; 1.2811x over previous
#include <cuda_runtime.h>
#include <cuda_fp16.h>
#include <math.h>
#include <stdint.h>

// Problem constants
#define B_  16
#define S_  8192
#define H_  512
#define M_  (B_ * S_)

// GEMM tiling
#define BM 128
#define BN 128
#define BK 32
#define NSLICE 4            // 512 / BN
#define NCHUNK 16           // 512 / BK
#define NSTAGE 3

// ---------------- scratch ----------------
__device__ __half g_ench[(size_t)M_ * H_];  // fp16 copy of enc (134 MB)
__device__ __half g_whh[H_ * H_];           // fp16 copy of W_h
__device__ float  g_qproj[B_ * H_];         // (B,H)
__device__ float  g_part[NSLICE][M_];       // score partials per N-slice
__device__ float  g_ctxpart[64][B_][H_];    // context partials

// ---------------- helpers ----------------
__device__ __forceinline__ uint32_t s2u(const void* p) {
    uint32_t a;
    asm("{ .reg .u64 t; cvta.to.shared.u64 t, %1; cvt.u32.u64 %0, t; }" : "=r"(a) : "l"(p));
    return a;
}
#define CP_ASYNC16(dst, src) \
    asm volatile("cp.async.cg.shared.global [%0], [%1], 16;" :: "r"(dst), "l"(src) : "memory")
#define CP_COMMIT()  asm volatile("cp.async.commit_group;" ::: "memory")
#define CP_WAIT1()   asm volatile("cp.async.wait_group 1;" ::: "memory")
#define CP_WAIT0()   asm volatile("cp.async.wait_group 0;" ::: "memory")

__device__ __forceinline__ void mma_f16(float* d, const uint32_t* a, const uint32_t* b) {
    asm volatile(
        "mma.sync.aligned.m16n8k16.row.col.f32.f16.f16.f32 "
        "{%0,%1,%2,%3}, {%4,%5,%6,%7}, {%8,%9}, {%0,%1,%2,%3};"
        : "+f"(d[0]), "+f"(d[1]), "+f"(d[2]), "+f"(d[3])
        : "r"(a[0]), "r"(a[1]), "r"(a[2]), "r"(a[3]), "r"(b[0]), "r"(b[1]));
}
__device__ __forceinline__ void ldsm_x4(uint32_t* r, uint32_t addr) {
    asm volatile("ldmatrix.sync.aligned.m8n8.x4.shared.b16 {%0,%1,%2,%3}, [%4];"
        : "=r"(r[0]), "=r"(r[1]), "=r"(r[2]), "=r"(r[3]) : "r"(addr));
}
__device__ __forceinline__ void ldsm_x2(uint32_t* r, uint32_t addr) {
    asm volatile("ldmatrix.sync.aligned.m8n8.x2.shared.b16 {%0,%1}, [%2];"
        : "=r"(r[0]), "=r"(r[1]) : "r"(addr));
}

// ---------------- SMEM layout (dynamic) ----------------
// Tiles are fp16: 128 rows x 32 cols = 64B/row, SW64 swizzle (unit ^= (r>>1)&3).
#define SM_QV     0                              // sq[128]+sv[128] = 1024B
#define SM_RED    1024                           // 128*4 floats = 2048B
#define SM_A      3072
#define A_STAGE   8192
#define SM_B      (SM_A + NSTAGE * A_STAGE)      // 27648
#define B_STAGE   8192
#define SMEM_TOTAL (SM_B + NSTAGE * B_STAGE)     // 52224 -> 2 CTAs/SM

// ---------------- kernel 0a: convert enc to fp16 ----------------
__global__ __launch_bounds__(256)
void cvt_enc_kernel(const float4* __restrict__ in)
{
    const size_t half_n = (size_t)M_ * H_ / 8;   // float4 count / 2
    size_t i = (size_t)blockIdx.x * 256 + threadIdx.x;
    uint2* out = (uint2*)g_ench;
    #pragma unroll
    for (int rep = 0; rep < 2; rep++) {
        size_t idx = i + rep * half_n;
        float4 t = in[idx];
        __half2 h0 = __floats2half2_rn(t.x, t.y);
        __half2 h1 = __floats2half2_rn(t.z, t.w);
        uint2 o;
        o.x = *(uint32_t*)&h0;
        o.y = *(uint32_t*)&h1;
        out[idx] = o;
    }
}

// ---------------- kernel 0b: convert W_h to fp16 ----------------
__global__ __launch_bounds__(256)
void cvt_wh_kernel(const float4* __restrict__ in)
{
    size_t i = (size_t)blockIdx.x * 256 + threadIdx.x;   // 65536 float4
    float4 t = in[i];
    __half2 h0 = __floats2half2_rn(t.x, t.y);
    __half2 h1 = __floats2half2_rn(t.z, t.w);
    uint2 o;
    o.x = *(uint32_t*)&h0;
    o.y = *(uint32_t*)&h1;
    ((uint2*)g_whh)[i] = o;
}

// ---------------- kernel 1: q_proj (fp32, exact) ----------------
__global__ void qproj_kernel(const float* __restrict__ query,
                             const float* __restrict__ Wq)
{
    int w = threadIdx.x >> 5, lane = threadIdx.x & 31;
    int o = blockIdx.x * 8 + w;
    int b = blockIdx.y;
    const float* q  = query + b * H_;
    const float* wr = Wq + o * H_;
    float s = 0.f;
    #pragma unroll 4
    for (int k = lane; k < H_; k += 32) s += q[k] * wr[k];
    #pragma unroll
    for (int off = 16; off > 0; off >>= 1) s += __shfl_xor_sync(0xffffffffu, s, off);
    if (lane == 0) g_qproj[b * H_ + o] = s;
}

// ---------------- kernel 2: fp16 mma.sync GEMM + fused tanh/v epilogue ----------------
// 256 threads, 8 warps: 2 over M (64 rows) x 4 over N (32 cols).
// 3-stage cp.async pipeline, one __syncthreads per chunk, 2 CTAs/SM.
// m16n8k16: 32 HMMA + 16 LDSM per chunk per warp.
__global__ __launch_bounds__(256, 2)
void score_gemm(const float* __restrict__ v)
{
    extern __shared__ char smem[];
    const uint32_t smem_u = s2u(smem);
    float* sq  = (float*)(smem + SM_QV);  // 128
    float* sv  = sq + 128;                // 128
    float* red = (float*)(smem + SM_RED); // 128 x 4

    const int tid  = threadIdx.x;
    const int wid  = tid >> 5;
    const int lane = tid & 31;
    const int g    = lane >> 2;           // fragment row
    const int c    = lane & 3;            // fragment col group
    const int wm   = wid & 1;             // 2 warps over M: 64 rows each
    const int wn   = wid >> 1;            // 4 warps over N: 32 cols each

    // ldmatrix source-lane roles
    const int rw  = lane & 7;             // row within 8x8 matrix
    const int roA = ((lane >> 3) & 1) << 3;  // A mats 1,3: +8 rows
    const int duA = lane >> 4;               // A mats 2,3: +8 k-cols (+1 unit)
    const int duB = (lane >> 3) & 1;         // B mat 1: +8 k-cols

    const int slice = blockIdx.x;         // slice-fast: 4 slices of one bm adjacent
    const int bm    = blockIdx.y;
    const int m0    = bm * BM;
    const int n0    = slice * BN;
    const int b     = m0 >> 13;

    if (tid < 128) {
        sq[tid] = g_qproj[b * H_ + n0 + tid];
        sv[tid] = v[n0 + tid];
    }

    // per-thread ldmatrix row byte-offsets + swizzle selectors
    uint32_t aRow[4], bRow[4];
    uint32_t sA[4], sB[4];
    #pragma unroll
    for (int mf = 0; mf < 4; mf++) {
        const int r = wm * 64 + mf * 16 + roA + rw;
        aRow[mf] = (uint32_t)r * 64;
        sA[mf]   = (uint32_t)((r >> 1) & 3);
    }
    #pragma unroll
    for (int nf = 0; nf < 4; nf++) {
        const int r = wn * 32 + nf * 8 + rw;
        bRow[nf] = (uint32_t)r * 64;
        sB[nf]   = (uint32_t)((r >> 1) & 3);
    }

    // accumulators: 4 m-frags x 4 n-frags x 4 regs
    float acc[4][4][4];
    #pragma unroll
    for (int i = 0; i < 4; i++)
        #pragma unroll
        for (int j = 0; j < 4; j++)
            #pragma unroll
            for (int k = 0; k < 4; k++) acc[i][j][k] = 0.f;

    const __half* Abase = g_ench + (size_t)m0 * H_;
    const __half* Bbase = g_whh + (size_t)n0 * H_;

    auto load_chunk = [&](int kc, int st) {
        const uint32_t abase = smem_u + SM_A + st * A_STAGE;
        const uint32_t bbase = smem_u + SM_B + st * B_STAGE;
        const __half* As = Abase + kc * BK;
        const __half* Bs = Bbase + kc * BK;
        #pragma unroll
        for (int i = 0; i < 2; i++) {             // A: 512 16B units
            int id = tid + i * 256;
            int r = id >> 2, u = id & 3;
            CP_ASYNC16(abase + r * 64 + ((u ^ ((r >> 1) & 3)) << 4),
                       As + (size_t)r * H_ + u * 8);
        }
        #pragma unroll
        for (int i = 0; i < 2; i++) {             // B: 512 16B units
            int id = tid + i * 256;
            int r = id >> 2, u = id & 3;
            CP_ASYNC16(bbase + r * 64 + ((u ^ ((r >> 1) & 3)) << 4),
                       Bs + (size_t)r * H_ + u * 8);
        }
        CP_COMMIT();
    };

    load_chunk(0, 0);
    load_chunk(1, 1);

    #pragma unroll 1
    for (int kc = 0; kc < NCHUNK; kc++) {
        const int st = kc % NSTAGE;
        if (kc + 2 < NCHUNK) CP_WAIT1(); else CP_WAIT0();
        __syncthreads();                          // chunk kc visible; stage (kc-1) consumed

        if (kc + 2 < NCHUNK) load_chunk(kc + 2, (kc + 2) % NSTAGE);

        const uint32_t abase = smem_u + SM_A + st * A_STAGE;
        const uint32_t bbase = smem_u + SM_B + st * B_STAGE;

        #pragma unroll
        for (int ks = 0; ks < 2; ks++) {          // two k16 steps per BK=32 chunk
            const uint32_t k2 = ks * 2;           // base 16B unit of this k-step

            uint32_t afr[4][4];
            #pragma unroll
            for (int mf = 0; mf < 4; mf++)
                ldsm_x4(afr[mf], abase + aRow[mf] + (((k2 + duA) ^ sA[mf]) << 4));

            uint32_t bfr[4][2];
            #pragma unroll
            for (int nf = 0; nf < 4; nf++)
                ldsm_x2(bfr[nf], bbase + bRow[nf] + (((k2 + duB) ^ sB[nf]) << 4));

            #pragma unroll
            for (int mf = 0; mf < 4; mf++)
                #pragma unroll
                for (int nf = 0; nf < 4; nf++)
                    mma_f16(acc[mf][nf], afr[mf], bfr[nf]);
        }
    }

    // ---- epilogue: tanh(C + q) * v, reduce over this CTA's 128 columns ----
    float rowsum[8];
    #pragma unroll
    for (int i = 0; i < 8; i++) rowsum[i] = 0.f;

    #pragma unroll
    for (int mf = 0; mf < 4; mf++) {
        #pragma unroll
        for (int nf = 0; nf < 4; nf++) {
            const int cb = wn * 32 + nf * 8 + 2 * c;
            const float q0 = sq[cb],     v0 = sv[cb];
            const float q1 = sq[cb + 1], v1 = sv[cb + 1];
            rowsum[mf * 2 + 0] += tanhf(acc[mf][nf][0] + q0) * v0
                                + tanhf(acc[mf][nf][1] + q1) * v1;
            rowsum[mf * 2 + 1] += tanhf(acc[mf][nf][2] + q0) * v0
                                + tanhf(acc[mf][nf][3] + q1) * v1;
        }
    }
    #pragma unroll
    for (int i = 0; i < 8; i++) {
        rowsum[i] += __shfl_xor_sync(0xffffffffu, rowsum[i], 1);
        rowsum[i] += __shfl_xor_sync(0xffffffffu, rowsum[i], 2);
    }
    if (c == 0) {
        #pragma unroll
        for (int i = 0; i < 8; i++) {
            const int mf = i >> 1, h = i & 1;
            const int row = wm * 64 + mf * 16 + g + h * 8;   // 0..127
            red[row * 4 + wn] = rowsum[i];
        }
    }
    __syncthreads();
    if (tid < BM) {
        g_part[slice][m0 + tid] = red[tid * 4 + 0] + red[tid * 4 + 1]
                                + red[tid * 4 + 2] + red[tid * 4 + 3];
    }
}

// ---------------- kernel 3: softmax ----------------
__global__ __launch_bounds__(1024)
void softmax_kernel(float* __restrict__ out_alpha)
{
    __shared__ float sm[32];
    const int b = blockIdx.x, tid = threadIdx.x;
    const int w = tid >> 5, lane = tid & 31;

    float sc[8];
    float mx = -1e30f;
    #pragma unroll
    for (int i = 0; i < 8; i++) {
        int m = b * S_ + tid + i * 1024;
        float x = g_part[0][m] + g_part[1][m] + g_part[2][m] + g_part[3][m];
        sc[i] = x;
        mx = fmaxf(mx, x);
    }
    #pragma unroll
    for (int off = 16; off > 0; off >>= 1) mx = fmaxf(mx, __shfl_xor_sync(0xffffffffu, mx, off));
    if (lane == 0) sm[w] = mx;
    __syncthreads();
    if (tid < 32) {
        float t = sm[tid];
        #pragma unroll
        for (int off = 16; off > 0; off >>= 1) t = fmaxf(t, __shfl_xor_sync(0xffffffffu, t, off));
        if (tid == 0) sm[0] = t;
    }
    __syncthreads();
    mx = sm[0];
    __syncthreads();

    float tot = 0.f;
    #pragma unroll
    for (int i = 0; i < 8; i++) { sc[i] = expf(sc[i] - mx); tot += sc[i]; }
    #pragma unroll
    for (int off = 16; off > 0; off >>= 1) tot += __shfl_xor_sync(0xffffffffu, tot, off);
    if (lane == 0) sm[w] = tot;
    __syncthreads();
    if (tid < 32) {
        float t = sm[tid];
        #pragma unroll
        for (int off = 16; off > 0; off >>= 1) t += __shfl_xor_sync(0xffffffffu, t, off);
        if (tid == 0) sm[0] = t;
    }
    __syncthreads();
    float inv = 1.f / sm[0];

    #pragma unroll
    for (int i = 0; i < 8; i++)
        out_alpha[b * S_ + tid + i * 1024] = sc[i] * inv;
}

// ---------------- kernel 4: context partials (fp16 enc, fp32 accumulate) ----------------
__global__ __launch_bounds__(128)
void ctx_part_kernel(const float* __restrict__ alpha)
{
    __shared__ float al[128];
    const int sch = blockIdx.x, b = blockIdx.y;
    const int tid = threadIdx.x;
    const int s0  = sch * 128;
    al[tid] = alpha[b * S_ + s0 + tid];
    __syncthreads();
    const uint2* e = (const uint2*)(g_ench + ((size_t)b * S_ + s0) * H_) + tid;  // 4 halfs/thread
    float4 acc = make_float4(0.f, 0.f, 0.f, 0.f);
    #pragma unroll 8
    for (int s = 0; s < 128; s++) {
        uint2 t = e[(size_t)s * (H_ / 4)];
        float2 f0 = __half22float2(*(__half2*)&t.x);
        float2 f1 = __half22float2(*(__half2*)&t.y);
        float  w = al[s];
        acc.x += w * f0.x; acc.y += w * f0.y;
        acc.z += w * f1.x; acc.w += w * f1.y;
    }
    ((float4*)&g_ctxpart[sch][b][0])[tid] = acc;
}

// ---------------- kernel 5: reduce context partials ----------------
__global__ __launch_bounds__(512)
void ctx_reduce_kernel(float* __restrict__ out_ctx)
{
    const int b = blockIdx.x, h = threadIdx.x;
    float s = 0.f;
    #pragma unroll
    for (int cidx = 0; cidx < 64; cidx++) s += g_ctxpart[cidx][b][h];
    out_ctx[b * H_ + h] = s;
}

// ---------------- launcher ----------------
extern "C" void kernel_launch(void* const* d_in, const int* in_sizes, int n_in,
                              void* d_out, int out_size)
{
    const float* enc   = (const float*)d_in[0];
    const float* query = (const float*)d_in[1];
    const float* Wh    = (const float*)d_in[2];
    const float* Wq    = (const float*)d_in[3];
    const float* v     = (const float*)d_in[4];

    float* out       = (float*)d_out;
    float* out_ctx   = out;
    float* out_alpha = out + B_ * H_;

    cudaFuncSetAttribute(score_gemm, cudaFuncAttributeMaxDynamicSharedMemorySize, SMEM_TOTAL);

    cvt_enc_kernel <<<32768, 256>>>((const float4*)enc);
    cvt_wh_kernel  <<<256, 256>>>((const float4*)Wh);
    qproj_kernel   <<<dim3(H_ / 8, B_), 256>>>(query, Wq);
    score_gemm     <<<dim3(NSLICE, M_ / BM), 256, SMEM_TOTAL>>>(v);
    softmax_kernel <<<B_, 1024>>>(out_alpha);
    ctx_part_kernel<<<dim3(64, B_), 128>>>(out_alpha);
    ctx_reduce_kernel<<<B_, 512>>>(out_ctx);
}

// round 16
// speedup vs baseline: 1.9799x; 1.0884x over previous
#include <cuda_runtime.h>
#include <cuda_fp16.h>
#include <math.h>
#include <stdint.h>

// Problem constants
#define B_  16
#define S_  8192
#define H_  512
#define M_  (B_ * S_)

// GEMM tiling
#define BM 128
#define BN 128
#define BK 64
#define NSLICE 4            // 512 / BN
#define NCHUNK 8            // 512 / BK
#define NSTAGE 3

// ---------------- scratch ----------------
__device__ __half g_ench[(size_t)M_ * H_];  // fp16 copy of enc (134 MB)
__device__ __half g_whh[H_ * H_];           // fp16 copy of W_h
__device__ float  g_qproj[B_ * H_];         // (B,H)
__device__ float  g_part[NSLICE][M_];       // score partials per N-slice
__device__ float  g_ctxpart[64][B_][H_];    // context partials

// ---------------- helpers ----------------
__device__ __forceinline__ uint32_t s2u(const void* p) {
    uint32_t a;
    asm("{ .reg .u64 t; cvta.to.shared.u64 t, %1; cvt.u32.u64 %0, t; }" : "=r"(a) : "l"(p));
    return a;
}
#define CP_ASYNC16(dst, src) \
    asm volatile("cp.async.cg.shared.global [%0], [%1], 16;" :: "r"(dst), "l"(src) : "memory")
#define CP_COMMIT()  asm volatile("cp.async.commit_group;" ::: "memory")
#define CP_WAIT1()   asm volatile("cp.async.wait_group 1;" ::: "memory")
#define CP_WAIT0()   asm volatile("cp.async.wait_group 0;" ::: "memory")

__device__ __forceinline__ void mma_f16(float* d, const uint32_t* a, const uint32_t* b) {
    asm volatile(
        "mma.sync.aligned.m16n8k16.row.col.f32.f16.f16.f32 "
        "{%0,%1,%2,%3}, {%4,%5,%6,%7}, {%8,%9}, {%0,%1,%2,%3};"
        : "+f"(d[0]), "+f"(d[1]), "+f"(d[2]), "+f"(d[3])
        : "r"(a[0]), "r"(a[1]), "r"(a[2]), "r"(a[3]), "r"(b[0]), "r"(b[1]));
}
__device__ __forceinline__ void ldsm_x4(uint32_t* r, uint32_t addr) {
    asm volatile("ldmatrix.sync.aligned.m8n8.x4.shared.b16 {%0,%1,%2,%3}, [%4];"
        : "=r"(r[0]), "=r"(r[1]), "=r"(r[2]), "=r"(r[3]) : "r"(addr));
}

// ---------------- SMEM layout (dynamic) ----------------
// Tiles fp16: 128 rows x 64 cols = 128B/row, SW128 swizzle (unit ^= r&7).
#define SM_QV     0                              // sq[128]+sv[128] = 1024B
#define SM_RED    1024                           // 128*4 floats = 2048B
#define SM_A      3072
#define A_STAGE   16384
#define SM_B      (SM_A + NSTAGE * A_STAGE)      // 52224
#define B_STAGE   16384
#define SMEM_TOTAL (SM_B + NSTAGE * B_STAGE)     // 101376 -> 2 CTAs/SM

// ---------------- kernel 0a: convert enc to fp16 ----------------
__global__ __launch_bounds__(256)
void cvt_enc_kernel(const float4* __restrict__ in)
{
    const size_t half_n = (size_t)M_ * H_ / 8;
    size_t i = (size_t)blockIdx.x * 256 + threadIdx.x;
    uint2* out = (uint2*)g_ench;
    #pragma unroll
    for (int rep = 0; rep < 2; rep++) {
        size_t idx = i + rep * half_n;
        float4 t = in[idx];
        __half2 h0 = __floats2half2_rn(t.x, t.y);
        __half2 h1 = __floats2half2_rn(t.z, t.w);
        uint2 o;
        o.x = *(uint32_t*)&h0;
        o.y = *(uint32_t*)&h1;
        out[idx] = o;
    }
}

// ---------------- kernel 0b: convert W_h to fp16 ----------------
__global__ __launch_bounds__(256)
void cvt_wh_kernel(const float4* __restrict__ in)
{
    size_t i = (size_t)blockIdx.x * 256 + threadIdx.x;
    float4 t = in[i];
    __half2 h0 = __floats2half2_rn(t.x, t.y);
    __half2 h1 = __floats2half2_rn(t.z, t.w);
    uint2 o;
    o.x = *(uint32_t*)&h0;
    o.y = *(uint32_t*)&h1;
    ((uint2*)g_whh)[i] = o;
}

// ---------------- kernel 1: q_proj (fp32, exact) ----------------
__global__ void qproj_kernel(const float* __restrict__ query,
                             const float* __restrict__ Wq)
{
    int w = threadIdx.x >> 5, lane = threadIdx.x & 31;
    int o = blockIdx.x * 8 + w;
    int b = blockIdx.y;
    const float* q  = query + b * H_;
    const float* wr = Wq + o * H_;
    float s = 0.f;
    #pragma unroll 4
    for (int k = lane; k < H_; k += 32) s += q[k] * wr[k];
    #pragma unroll
    for (int off = 16; off > 0; off >>= 1) s += __shfl_xor_sync(0xffffffffu, s, off);
    if (lane == 0) g_qproj[b * H_ + o] = s;
}

// ---------------- kernel 2: fp16 mma.sync GEMM + fused tanh/v epilogue ----------------
// 256 threads, 8 warps (2 over M x 4 over N), BK=64 chunks, 3-stage pipeline,
// one __syncthreads per chunk, 2 CTAs/SM.
// Per chunk per warp: 24 LDSM.x4 + 64 HMMA (paired-B x4 loads).
__global__ __launch_bounds__(256, 2)
void score_gemm(const float* __restrict__ v)
{
    extern __shared__ char smem[];
    const uint32_t smem_u = s2u(smem);
    float* sq  = (float*)(smem + SM_QV);  // 128
    float* sv  = sq + 128;                // 128
    float* red = (float*)(smem + SM_RED); // 128 x 4

    const int tid  = threadIdx.x;
    const int wid  = tid >> 5;
    const int lane = tid & 31;
    const int g    = lane >> 2;           // fragment row (epilogue)
    const int c    = lane & 3;            // fragment col group (epilogue)
    const int wm   = wid & 1;             // 2 warps over M: 64 rows each
    const int wn   = wid >> 1;            // 4 warps over N: 32 cols each

    const int rw   = lane & 7;            // ldmatrix row-within-matrix & swizzle selector
    // A x4 roles: mats {0,1} rows +0/+8; mats {2,3} same rows, k+8 (next 16B unit)
    const int roA  = ((lane >> 3) & 1) << 3;
    const int duA  = lane >> 4;
    // B paired x4 roles: mats {0,1} = nf_even (k0,k1 units); {2,3} = nf_odd
    const int nfoB = ((lane >> 4) & 1) << 3;   // +8 rows for odd nf of the pair
    const int kuB  = (lane >> 3) & 1;          // k-unit within k16

    const int slice = blockIdx.x;         // slice-fast: 4 slices of one bm adjacent
    const int bm    = blockIdx.y;
    const int m0    = bm * BM;
    const int n0    = slice * BN;
    const int b     = m0 >> 13;

    if (tid < 128) {
        sq[tid] = g_qproj[b * H_ + n0 + tid];
        sv[tid] = v[n0 + tid];
    }

    // per-thread ldmatrix row byte-offsets (rows are multiples of 8 + rw -> selector = rw)
    uint32_t aRow[4], bRowP[2];
    #pragma unroll
    for (int mf = 0; mf < 4; mf++)
        aRow[mf] = (uint32_t)(wm * 64 + mf * 16 + roA + rw) * 128;
    #pragma unroll
    for (int p = 0; p < 2; p++)
        bRowP[p] = (uint32_t)(wn * 32 + p * 16 + nfoB + rw) * 128;

    // accumulators: 4 m-frags x 4 n-frags x 4 regs
    float acc[4][4][4];
    #pragma unroll
    for (int i = 0; i < 4; i++)
        #pragma unroll
        for (int j = 0; j < 4; j++)
            #pragma unroll
            for (int k = 0; k < 4; k++) acc[i][j][k] = 0.f;

    const __half* Abase = g_ench + (size_t)m0 * H_;
    const __half* Bbase = g_whh + (size_t)n0 * H_;

    auto load_chunk = [&](int kc, int st) {
        const uint32_t abase = smem_u + SM_A + st * A_STAGE;
        const uint32_t bbase = smem_u + SM_B + st * B_STAGE;
        const __half* As = Abase + kc * BK;
        const __half* Bs = Bbase + kc * BK;
        #pragma unroll
        for (int i = 0; i < 4; i++) {             // A: 1024 16B units
            int id = tid + i * 256;
            int r = id >> 3, u = id & 7;
            CP_ASYNC16(abase + r * 128 + ((u ^ (r & 7)) << 4),
                       As + (size_t)r * H_ + u * 8);
        }
        #pragma unroll
        for (int i = 0; i < 4; i++) {             // B: 1024 16B units
            int id = tid + i * 256;
            int r = id >> 3, u = id & 7;
            CP_ASYNC16(bbase + r * 128 + ((u ^ (r & 7)) << 4),
                       Bs + (size_t)r * H_ + u * 8);
        }
        CP_COMMIT();
    };

    load_chunk(0, 0);
    load_chunk(1, 1);

    #pragma unroll 1
    for (int kc = 0; kc < NCHUNK; kc++) {
        const int st = kc % NSTAGE;
        if (kc + 2 < NCHUNK) CP_WAIT1(); else CP_WAIT0();
        __syncthreads();                          // chunk kc visible; stage (kc-1) consumed

        if (kc + 2 < NCHUNK) load_chunk(kc + 2, (kc + 2) % NSTAGE);

        const uint32_t abase = smem_u + SM_A + st * A_STAGE;
        const uint32_t bbase = smem_u + SM_B + st * B_STAGE;

        #pragma unroll
        for (int ks = 0; ks < 4; ks++) {          // four k16 steps per BK=64 chunk
            const uint32_t k2 = ks * 2;

            uint32_t afr[4][4];
            #pragma unroll
            for (int mf = 0; mf < 4; mf++)
                ldsm_x4(afr[mf], abase + aRow[mf] + (((k2 + duA) ^ rw) << 4));

            uint32_t bfr[4][2];
            #pragma unroll
            for (int p = 0; p < 2; p++) {
                uint32_t bq[4];
                ldsm_x4(bq, bbase + bRowP[p] + (((k2 + kuB) ^ rw) << 4));
                bfr[2 * p + 0][0] = bq[0]; bfr[2 * p + 0][1] = bq[1];
                bfr[2 * p + 1][0] = bq[2]; bfr[2 * p + 1][1] = bq[3];
            }

            #pragma unroll
            for (int mf = 0; mf < 4; mf++)
                #pragma unroll
                for (int nf = 0; nf < 4; nf++)
                    mma_f16(acc[mf][nf], afr[mf], bfr[nf]);
        }
    }

    // ---- epilogue: tanh(C + q) * v, reduce over this CTA's 128 columns ----
    float rowsum[8];
    #pragma unroll
    for (int i = 0; i < 8; i++) rowsum[i] = 0.f;

    #pragma unroll
    for (int mf = 0; mf < 4; mf++) {
        #pragma unroll
        for (int nf = 0; nf < 4; nf++) {
            const int cb = wn * 32 + nf * 8 + 2 * c;
            const float q0 = sq[cb],     v0 = sv[cb];
            const float q1 = sq[cb + 1], v1 = sv[cb + 1];
            rowsum[mf * 2 + 0] += tanhf(acc[mf][nf][0] + q0) * v0
                                + tanhf(acc[mf][nf][1] + q1) * v1;
            rowsum[mf * 2 + 1] += tanhf(acc[mf][nf][2] + q0) * v0
                                + tanhf(acc[mf][nf][3] + q1) * v1;
        }
    }
    #pragma unroll
    for (int i = 0; i < 8; i++) {
        rowsum[i] += __shfl_xor_sync(0xffffffffu, rowsum[i], 1);
        rowsum[i] += __shfl_xor_sync(0xffffffffu, rowsum[i], 2);
    }
    if (c == 0) {
        #pragma unroll
        for (int i = 0; i < 8; i++) {
            const int mf = i >> 1, h = i & 1;
            const int row = wm * 64 + mf * 16 + g + h * 8;   // 0..127
            red[row * 4 + wn] = rowsum[i];
        }
    }
    __syncthreads();
    if (tid < BM) {
        g_part[slice][m0 + tid] = red[tid * 4 + 0] + red[tid * 4 + 1]
                                + red[tid * 4 + 2] + red[tid * 4 + 3];
    }
}

// ---------------- kernel 3: softmax ----------------
__global__ __launch_bounds__(1024)
void softmax_kernel(float* __restrict__ out_alpha)
{
    __shared__ float sm[32];
    const int b = blockIdx.x, tid = threadIdx.x;
    const int w = tid >> 5, lane = tid & 31;

    float sc[8];
    float mx = -1e30f;
    #pragma unroll
    for (int i = 0; i < 8; i++) {
        int m = b * S_ + tid + i * 1024;
        float x = g_part[0][m] + g_part[1][m] + g_part[2][m] + g_part[3][m];
        sc[i] = x;
        mx = fmaxf(mx, x);
    }
    #pragma unroll
    for (int off = 16; off > 0; off >>= 1) mx = fmaxf(mx, __shfl_xor_sync(0xffffffffu, mx, off));
    if (lane == 0) sm[w] = mx;
    __syncthreads();
    if (tid < 32) {
        float t = sm[tid];
        #pragma unroll
        for (int off = 16; off > 0; off >>= 1) t = fmaxf(t, __shfl_xor_sync(0xffffffffu, t, off));
        if (tid == 0) sm[0] = t;
    }
    __syncthreads();
    mx = sm[0];
    __syncthreads();

    float tot = 0.f;
    #pragma unroll
    for (int i = 0; i < 8; i++) { sc[i] = expf(sc[i] - mx); tot += sc[i]; }
    #pragma unroll
    for (int off = 16; off > 0; off >>= 1) tot += __shfl_xor_sync(0xffffffffu, tot, off);
    if (lane == 0) sm[w] = tot;
    __syncthreads();
    if (tid < 32) {
        float t = sm[tid];
        #pragma unroll
        for (int off = 16; off > 0; off >>= 1) t += __shfl_xor_sync(0xffffffffu, t, off);
        if (tid == 0) sm[0] = t;
    }
    __syncthreads();
    float inv = 1.f / sm[0];

    #pragma unroll
    for (int i = 0; i < 8; i++)
        out_alpha[b * S_ + tid + i * 1024] = sc[i] * inv;
}

// ---------------- kernel 4: context partials (fp16 enc, fp32 accumulate) ----------------
__global__ __launch_bounds__(128)
void ctx_part_kernel(const float* __restrict__ alpha)
{
    __shared__ float al[128];
    const int sch = blockIdx.x, b = blockIdx.y;
    const int tid = threadIdx.x;
    const int s0  = sch * 128;
    al[tid] = alpha[b * S_ + s0 + tid];
    __syncthreads();
    const uint2* e = (const uint2*)(g_ench + ((size_t)b * S_ + s0) * H_) + tid;
    float4 acc = make_float4(0.f, 0.f, 0.f, 0.f);
    #pragma unroll 8
    for (int s = 0; s < 128; s++) {
        uint2 t = e[(size_t)s * (H_ / 4)];
        float2 f0 = __half22float2(*(__half2*)&t.x);
        float2 f1 = __half22float2(*(__half2*)&t.y);
        float  w = al[s];
        acc.x += w * f0.x; acc.y += w * f0.y;
        acc.z += w * f1.x; acc.w += w * f1.y;
    }
    ((float4*)&g_ctxpart[sch][b][0])[tid] = acc;
}

// ---------------- kernel 5: reduce context partials ----------------
__global__ __launch_bounds__(512)
void ctx_reduce_kernel(float* __restrict__ out_ctx)
{
    const int b = blockIdx.x, h = threadIdx.x;
    float s = 0.f;
    #pragma unroll
    for (int cidx = 0; cidx < 64; cidx++) s += g_ctxpart[cidx][b][h];
    out_ctx[b * H_ + h] = s;
}

// ---------------- launcher ----------------
extern "C" void kernel_launch(void* const* d_in, const int* in_sizes, int n_in,
                              void* d_out, int out_size)
{
    const float* enc   = (const float*)d_in[0];
    const float* query = (const float*)d_in[1];
    const float* Wh    = (const float*)d_in[2];
    const float* Wq    = (const float*)d_in[3];
    const float* v     = (const float*)d_in[4];

    float* out       = (float*)d_out;
    float* out_ctx   = out;
    float* out_alpha = out + B_ * H_;

    cudaFuncSetAttribute(score_gemm, cudaFuncAttributeMaxDynamicSharedMemorySize, SMEM_TOTAL);

    cvt_enc_kernel <<<32768, 256>>>((const float4*)enc);
    cvt_wh_kernel  <<<256, 256>>>((const float4*)Wh);
    qproj_kernel   <<<dim3(H_ / 8, B_), 256>>>(query, Wq);
    score_gemm     <<<dim3(NSLICE, M_ / BM), 256, SMEM_TOTAL>>>(v);
    softmax_kernel <<<B_, 1024>>>(out_alpha);
    ctx_part_kernel<<<dim3(64, B_), 128>>>(out_alpha);
    ctx_reduce_kernel<<<B_, 512>>>(out_ctx);
}